// round 4
// baseline (speedup 1.0000x reference)
#include <cuda_runtime.h>
#include <cstdint>

#define MAX_SEG 100001

// scratch (no cudaMalloc allowed)
__device__ int g_offsets[MAX_SEG + 1];

// ---------------------------------------------------------------------------
// Inline dtype detection (reference declares int64; JAX w/o x64 emits int32).
// For little-endian int64 indices in [0, 2^31), every odd int32 word is 0.
// For int32 data those words are uniform random gather indices;
// P(first 8 all zero) ~ 1e-42. One broadcast sector load + one vote.
// ---------------------------------------------------------------------------
__device__ __forceinline__ bool detect_is64_warp(const void* gidx, int lane) {
    const int* p = (const int*)gidx;
    int w = (lane < 8) ? p[2 * lane + 1] : 0;
    return __all_sync(0xFFFFFFFFu, w == 0);
}

__device__ __forceinline__ int load_idx(const void* p, int i, bool is64) {
    return is64 ? (int)((const long long*)p)[i] : ((const int*)p)[i];
}

// ---------------------------------------------------------------------------
// CSR offsets from sorted segment ids. offsets[s] = first edge with seg >= s.
// ---------------------------------------------------------------------------
__global__ void build_offsets_kernel(const void* __restrict__ seg,
                                     const void* __restrict__ gidx,
                                     int E, int nseg) {
    int e = blockIdx.x * blockDim.x + threadIdx.x;
    bool is64 = detect_is64_warp(gidx, threadIdx.x & 31);
    if (e >= E) return;
    int cur = load_idx(seg, e, is64);
    int prev = (e == 0) ? -1 : load_idx(seg, e - 1, is64);
    for (int s = prev + 1; s <= cur; s++) g_offsets[s] = e;
    if (e == E - 1) {
        for (int s = cur + 1; s <= nseg; s++) g_offsets[s] = E;
    }
}

// ---------------------------------------------------------------------------
// One warp per segment. Lane layout: l16 = float4 slot within the 256B row
// (16 lanes cover a row), half = lane>>4 selects which of two rows this lane
// reads. One LDG.128 instruction therefore fetches TWO gathered rows.
// Indices are loaded once per 32-edge chunk with a single coalesced load and
// distributed via __shfl_sync (no idx->row memory dependency). Unroll x4
// keeps 8 independent row reads (2KB) in flight per warp.
// ---------------------------------------------------------------------------
__global__ void __launch_bounds__(128)
seg_mean_kernel(const float* __restrict__ values,
                const void* __restrict__ gidx,
                float* __restrict__ out, int nseg) {
    int lane = threadIdx.x & 31;
    bool is64 = detect_is64_warp(gidx, lane);

    int warp = (blockIdx.x * blockDim.x + threadIdx.x) >> 5;
    if (warp >= nseg) return;

    int half = lane >> 4;      // which row of the pair
    int l16  = lane & 15;      // float4 slot within row

    int start = g_offsets[warp];
    int end   = g_offsets[warp + 1];
    int n     = end - start;

    const char* vbase = (const char*)values + l16 * 16;  // lane's slot base

    float4 a0 = {0.f,0.f,0.f,0.f}, a1 = {0.f,0.f,0.f,0.f};
    float4 a2 = {0.f,0.f,0.f,0.f}, a3 = {0.f,0.f,0.f,0.f};

    for (int base = 0; base < n; base += 32) {
        int m = n - base;
        if (m > 32) m = 32;
        // one coalesced load of up to 32 indices for this chunk
        int myidx = 0;
        if (lane < m) myidx = load_idx(gidx, start + base + lane, is64);

        int j = 0;
        // main: 8 rows per iteration via 4 LDG.128 (2 rows each)
        for (; j + 8 <= m; j += 8) {
            int i0 = __shfl_sync(0xFFFFFFFFu, myidx, j + 0 + half);
            int i1 = __shfl_sync(0xFFFFFFFFu, myidx, j + 2 + half);
            int i2 = __shfl_sync(0xFFFFFFFFu, myidx, j + 4 + half);
            int i3 = __shfl_sync(0xFFFFFFFFu, myidx, j + 6 + half);
            float4 v0 = *(const float4*)(vbase + (unsigned)i0 * 256u);
            float4 v1 = *(const float4*)(vbase + (unsigned)i1 * 256u);
            float4 v2 = *(const float4*)(vbase + (unsigned)i2 * 256u);
            float4 v3 = *(const float4*)(vbase + (unsigned)i3 * 256u);
            a0.x += v0.x; a0.y += v0.y; a0.z += v0.z; a0.w += v0.w;
            a1.x += v1.x; a1.y += v1.y; a1.z += v1.z; a1.w += v1.w;
            a2.x += v2.x; a2.y += v2.y; a2.z += v2.z; a2.w += v2.w;
            a3.x += v3.x; a3.y += v3.y; a3.z += v3.z; a3.w += v3.w;
        }
        // tail: 2 rows per iteration, weighted FMA for the odd row
        for (; j < m; j += 2) {
            int jj  = j + half;
            int src = jj < m ? jj : (m - 1);
            int i0  = __shfl_sync(0xFFFFFFFFu, myidx, src);
            float4 v0 = *(const float4*)(vbase + (unsigned)i0 * 256u);
            float w = jj < m ? 1.0f : 0.0f;
            a0.x += w * v0.x; a0.y += w * v0.y;
            a0.z += w * v0.z; a0.w += w * v0.w;
        }
    }

    float sx = (a0.x + a1.x) + (a2.x + a3.x);
    float sy = (a0.y + a1.y) + (a2.y + a3.y);
    float sz = (a0.z + a1.z) + (a2.z + a3.z);
    float sw = (a0.w + a1.w) + (a2.w + a3.w);

    // combine the two halves (same l16 slot, xor lane bit 4)
    sx += __shfl_xor_sync(0xFFFFFFFFu, sx, 16);
    sy += __shfl_xor_sync(0xFFFFFFFFu, sy, 16);
    sz += __shfl_xor_sync(0xFFFFFFFFu, sz, 16);
    sw += __shfl_xor_sync(0xFFFFFFFFu, sw, 16);

    float inv = 1.0f / (float)(n > 0 ? n : 1);
    if (half == 0) {
        float4 r = {sx * inv, sy * inv, sz * inv, sw * inv};
        ((float4*)(out + (long long)warp * 64))[l16] = r;
    }
}

// ---------------------------------------------------------------------------
// launch
// inputs: 0=values [N_SRC,64] f32, 1=gather_idx [E] i64/i32,
//         2=segment_ids [E] i64/i32 (sorted), 3=num_segments (scalar, unused)
// out: [nseg,64] f32, nseg = out_size/64
// ---------------------------------------------------------------------------
extern "C" void kernel_launch(void* const* d_in, const int* in_sizes, int n_in,
                              void* d_out, int out_size) {
    const float* values = (const float*)d_in[0];
    const void*  gidx   = d_in[1];
    const void*  seg    = d_in[2];
    float* out = (float*)d_out;

    int E    = in_sizes[1];
    int nseg = out_size / 64;
    if (nseg > MAX_SEG) nseg = MAX_SEG;

    int bthreads = 256;
    build_offsets_kernel<<<(E + bthreads - 1) / bthreads, bthreads>>>(seg, gidx, E, nseg);

    int threads = 128;
    int warps_per_block = threads / 32;
    int blocks = (nseg + warps_per_block - 1) / warps_per_block;
    seg_mean_kernel<<<blocks, threads>>>(values, gidx, out, nseg);
}

// round 5
// speedup vs baseline: 1.2850x; 1.2850x over previous
#include <cuda_runtime.h>
#include <cstdint>

#define MAX_SEG 100001
#define SEGS_PER_BLOCK 4
#define SMEM_IDX 1024   // indices staged per block (4 segments, mean ~51 edges)

// scratch (no cudaMalloc allowed)
__device__ int g_offsets[MAX_SEG + 1];

// ---------------------------------------------------------------------------
// Inline dtype detection (reference declares int64; JAX w/o x64 emits int32).
// For little-endian int64 indices in [0, 2^31), every odd int32 word is 0.
// For int32 data those words are uniform random gather indices;
// P(first 8 all zero) ~ 1e-42. One broadcast sector load + one vote.
// ---------------------------------------------------------------------------
__device__ __forceinline__ bool detect_is64_warp(const void* gidx, int lane) {
    const int* p = (const int*)gidx;
    int w = (lane < 8) ? p[2 * lane + 1] : 0;
    return __all_sync(0xFFFFFFFFu, w == 0);
}

__device__ __forceinline__ int load_idx(const void* p, int i, bool is64) {
    return is64 ? (int)((const long long*)p)[i] : ((const int*)p)[i];
}

// ---------------------------------------------------------------------------
// CSR offsets from sorted segment ids. offsets[s] = first edge with seg >= s.
// ---------------------------------------------------------------------------
__global__ void build_offsets_kernel(const void* __restrict__ seg,
                                     const void* __restrict__ gidx,
                                     int E, int nseg) {
    int e = blockIdx.x * blockDim.x + threadIdx.x;
    bool is64 = detect_is64_warp(gidx, threadIdx.x & 31);
    if (e >= E) return;
    int cur = load_idx(seg, e, is64);
    int prev = (e == 0) ? -1 : load_idx(seg, e - 1, is64);
    for (int s = prev + 1; s <= cur; s++) g_offsets[s] = e;
    if (e == E - 1) {
        for (int s = cur + 1; s <= nseg; s++) g_offsets[s] = E;
    }
}

// ---------------------------------------------------------------------------
// Block = 4 warps = 4 consecutive segments (contiguous edge range, ids are
// sorted). The block stages all its gather indices into smem with one
// coalesced sweep, then each warp runs the row loop: lane owns a float2
// slice of the 256B row, indices come from broadcast LDS (conflict-free),
// unroll x4 keeps 4 independent 256B row reads in flight per warp.
// ---------------------------------------------------------------------------
__global__ void __launch_bounds__(128)
seg_mean_kernel(const float* __restrict__ values,
                const void* __restrict__ gidx,
                float* __restrict__ out, int nseg) {
    __shared__ int s_idx[SMEM_IDX];
    __shared__ int s_off[SEGS_PER_BLOCK + 1];

    int tid  = threadIdx.x;
    int lane = tid & 31;
    int w    = tid >> 5;
    int seg0 = blockIdx.x * SEGS_PER_BLOCK;
    bool is64 = detect_is64_warp(gidx, lane);

    if (tid <= SEGS_PER_BLOCK) {
        int s = seg0 + tid;
        s_off[tid] = g_offsets[s < nseg ? s : nseg];
    }
    __syncthreads();

    int estart = s_off[0];
    int etot   = s_off[SEGS_PER_BLOCK] - estart;
    int nsm    = etot < SMEM_IDX ? etot : SMEM_IDX;

    // coalesced stage of all block indices into smem (int64 -> int32 on load)
    for (int i = tid; i < nsm; i += 128)
        s_idx[i] = load_idx(gidx, estart + i, is64);
    __syncthreads();

    int seg = seg0 + w;
    if (seg >= nseg) return;

    int start = s_off[w]     - estart;   // block-local edge range
    int end   = s_off[w + 1] - estart;
    int n     = end - start;

    const char* vb = (const char*)values + lane * 8;  // lane's float2 slot

    float2 a0 = {0.f, 0.f}, a1 = {0.f, 0.f}, a2 = {0.f, 0.f}, a3 = {0.f, 0.f};

    if (end <= nsm) {
        // fast path: all indices staged in smem
        int e = start;
        for (; e + 4 <= end; e += 4) {
            int i0 = s_idx[e + 0];
            int i1 = s_idx[e + 1];
            int i2 = s_idx[e + 2];
            int i3 = s_idx[e + 3];
            float2 v0 = *(const float2*)(vb + (unsigned)i0 * 256u);
            float2 v1 = *(const float2*)(vb + (unsigned)i1 * 256u);
            float2 v2 = *(const float2*)(vb + (unsigned)i2 * 256u);
            float2 v3 = *(const float2*)(vb + (unsigned)i3 * 256u);
            a0.x += v0.x; a0.y += v0.y;
            a1.x += v1.x; a1.y += v1.y;
            a2.x += v2.x; a2.y += v2.y;
            a3.x += v3.x; a3.y += v3.y;
        }
        for (; e < end; e++) {
            int i0 = s_idx[e];
            float2 v0 = *(const float2*)(vb + (unsigned)i0 * 256u);
            a0.x += v0.x; a0.y += v0.y;
        }
    } else {
        // overflow fallback (essentially never taken): idx straight from gmem
        for (int e = start; e < end; e++) {
            int i0 = (e < nsm) ? s_idx[e] : load_idx(gidx, estart + e, is64);
            float2 v0 = *(const float2*)(vb + (unsigned)i0 * 256u);
            a0.x += v0.x; a0.y += v0.y;
        }
    }

    float sx = (a0.x + a1.x) + (a2.x + a3.x);
    float sy = (a0.y + a1.y) + (a2.y + a3.y);

    float inv = 1.0f / (float)(n > 0 ? n : 1);
    float2 r = {sx * inv, sy * inv};
    ((float2*)(out + (long long)seg * 64))[lane] = r;
}

// ---------------------------------------------------------------------------
// launch
// inputs: 0=values [N_SRC,64] f32, 1=gather_idx [E] i64/i32,
//         2=segment_ids [E] i64/i32 (sorted), 3=num_segments (scalar, unused)
// out: [nseg,64] f32, nseg = out_size/64
// ---------------------------------------------------------------------------
extern "C" void kernel_launch(void* const* d_in, const int* in_sizes, int n_in,
                              void* d_out, int out_size) {
    const float* values = (const float*)d_in[0];
    const void*  gidx   = d_in[1];
    const void*  seg    = d_in[2];
    float* out = (float*)d_out;

    int E    = in_sizes[1];
    int nseg = out_size / 64;
    if (nseg > MAX_SEG) nseg = MAX_SEG;

    int bthreads = 256;
    build_offsets_kernel<<<(E + bthreads - 1) / bthreads, bthreads>>>(seg, gidx, E, nseg);

    int blocks = (nseg + SEGS_PER_BLOCK - 1) / SEGS_PER_BLOCK;
    seg_mean_kernel<<<blocks, 128>>>(values, gidx, out, nseg);
}